// round 2
// baseline (speedup 1.0000x reference)
#include <cuda_runtime.h>

#define D 64
#define GMAX 64
#define NMAX 100000
#define EMAX 1250000

// ---- scratch (device globals: no allocation allowed). float4 => 16B alignment. ----
__device__ float4 g_h4[NMAX * D / 4];     // h' = (x @ W) * dis[row]
__device__ float4 g_agg4[NMAX * D / 4];   // scatter accumulator (init = h' -> self loop folded)
__device__ float4 g_buf04[NMAX * D / 4];  // layer ping-pong
__device__ float4 g_buf14[NMAX * D / 4];
__device__ float g_deg[NMAX];
__device__ float g_dis[NMAX];
__device__ float g_cnt[GMAX];
__device__ float g_gmax[GMAX * D];
__device__ float g_gsum[GMAX * D];

#define g_h ((float*)g_h4)
#define g_agg ((float*)g_agg4)

// ---- init: deg=1 (self loop), zero counters / pool buffers / graph output ----
__global__ void k_init(float* __restrict__ out_graph, int n) {
    int i = blockIdx.x * blockDim.x + threadIdx.x;
    if (i < n) g_deg[i] = 1.0f;
    if (i < GMAX) g_cnt[i] = 0.0f;
    if (i < GMAX * D) { g_gmax[i] = 0.0f; g_gsum[i] = 0.0f; }
    if (i < GMAX * 2 * D) out_graph[i] = 0.0f;
}

// ---- degree over destinations ----
__global__ void k_deg(const int* __restrict__ ei, int e) {
    int i = blockIdx.x * blockDim.x + threadIdx.x;
    if (i < e) atomicAdd(&g_deg[ei[e + i]], 1.0f);
}

// ---- dis = rsqrt(deg); per-graph node counts ----
__global__ void k_dis(const int* __restrict__ batch, int n) {
    int i = blockIdx.x * blockDim.x + threadIdx.x;
    if (i < n) {
        g_dis[i] = rsqrtf(g_deg[i]);
        atomicAdd(&g_cnt[batch[i]], 1.0f);
    }
}

// ---- h' = (x @ W) * dis[row]; agg initialized to h' (self-loop term) ----
// 64 rows per block, 256 threads: 4 threads/row, 16 cols each (stride-4 smem reads)
__global__ void k_gemm(const float* __restrict__ x, const float* __restrict__ W, int n) {
    __shared__ float xs[64 * 68];   // stride 68: conflict-free xs[r*68+k] reads
    __shared__ float ws[64 * 64];
    int t = threadIdx.x;
    int R0 = blockIdx.x * 64;
    int rows = min(64, n - R0);

    for (int i = t; i < 64 * 16; i += 256)
        ((float4*)ws)[i] = ((const float4*)W)[i];
    for (int i = t; i < rows * 16; i += 256) {
        int rr = i >> 4, c4 = i & 15;
        *((float4*)(xs + rr * 68) + c4) = *((const float4*)(x + (size_t)(R0 + rr) * 64) + c4);
    }
    __syncthreads();

    int r = t >> 2;      // 0..63
    int c = t & 3;       // 0..3
    if (r >= rows) return;

    float acc[16];
#pragma unroll
    for (int j = 0; j < 16; j++) acc[j] = 0.0f;
#pragma unroll
    for (int k = 0; k < 64; k++) {
        float xv = xs[r * 68 + k];
        const float* wrow = ws + k * 64;
#pragma unroll
        for (int j = 0; j < 16; j++) acc[j] += xv * wrow[4 * j + c];
    }
    int gr = R0 + r;
    float s = g_dis[gr];
    float* hp = g_h + (size_t)gr * 64;
    float* ap = g_agg + (size_t)gr * 64;
#pragma unroll
    for (int j = 0; j < 16; j++) {
        float v = acc[j] * s;
        hp[4 * j + c] = v;
        ap[4 * j + c] = v;
    }
}

// ---- edge scatter: agg[dst] += h'[src]; 16 threads/edge, float4 gather + 4 atomics ----
__global__ void k_scatter(const int* __restrict__ ei, int e) {
    int idx = blockIdx.x * blockDim.x + threadIdx.x;
    int eid = idx >> 4;
    if (eid >= e) return;
    int chunk = (idx & 15) << 2;             // 0,4,...,60
    int src = ei[eid];
    int dst = ei[e + eid];
    float4 v = *(const float4*)(g_h + (size_t)src * 64 + chunk);
    float* a = g_agg + (size_t)dst * 64 + chunk;
    atomicAdd(a + 0, v.x);
    atomicAdd(a + 1, v.y);
    atomicAdd(a + 2, v.z);
    atomicAdd(a + 3, v.w);
}

// ---- epilogue: x_out = relu(dis*agg + b) + graph max/mean pooling ----
// 128 rows/block, 256 threads: thread = (rr in 0..3, dim j). Block-local smem reduce
// when the whole 128-row stripe belongs to one graph (batch sorted -> common case).
__global__ void k_epilogue(const float* __restrict__ b, const int* __restrict__ batch,
                           float* __restrict__ xout, int n) {
    int t = threadIdx.x;
    int j = t & 63;
    int rr = t >> 6;
    int R0 = blockIdx.x * 128;
    int rows = min(128, n - R0);
    int gfirst = batch[R0];
    int glast = batch[R0 + rows - 1];
    bool uniform = (gfirst == glast);
    float bj = b[j];

    float lsum = 0.0f, lmax = 0.0f;
    for (int k = rr; k < rows; k += 4) {
        int r = R0 + k;
        float v = fmaf(g_dis[r], g_agg[(size_t)r * 64 + j], bj);
        v = fmaxf(v, 0.0f);
        xout[(size_t)r * 64 + j] = v;
        if (uniform) {
            lsum += v;
            lmax = fmaxf(lmax, v);
        } else {
            int g = batch[r];
            atomicAdd(&g_gsum[g * 64 + j], v);
            atomicMax((unsigned int*)&g_gmax[g * 64 + j], __float_as_uint(v));
        }
    }
    if (uniform) {
        __shared__ float ssum[4][64];
        __shared__ float smax[4][64];
        ssum[rr][j] = lsum;
        smax[rr][j] = lmax;
        __syncthreads();
        if (rr == 0) {
            float s = ssum[0][j] + ssum[1][j] + ssum[2][j] + ssum[3][j];
            float m = fmaxf(fmaxf(smax[0][j], smax[1][j]), fmaxf(smax[2][j], smax[3][j]));
            atomicAdd(&g_gsum[gfirst * 64 + j], s);
            atomicMax((unsigned int*)&g_gmax[gfirst * 64 + j], __float_as_uint(m));
        }
    }
}

// ---- accumulate per-layer pooled features into graph output; reset pool buffers ----
__global__ void k_graphacc(float* __restrict__ out_graph) {
    int i = blockIdx.x * blockDim.x + threadIdx.x;
    if (i >= GMAX * 64) return;
    int g = i >> 6, j = i & 63;
    out_graph[g * 128 + j] += g_gmax[i];
    out_graph[g * 128 + 64 + j] += g_gsum[i] / g_cnt[g];
    g_gmax[i] = 0.0f;
    g_gsum[i] = 0.0f;
}

extern "C" void kernel_launch(void* const* d_in, const int* in_sizes, int n_in,
                              void* d_out, int out_size) {
    const float* x = (const float*)d_in[0];
    const int* ei = (const int*)d_in[1];
    const int* batch = (const int*)d_in[2];
    const float* Ws[3] = {(const float*)d_in[3], (const float*)d_in[5], (const float*)d_in[7]};
    const float* bs[3] = {(const float*)d_in[4], (const float*)d_in[6], (const float*)d_in[8]};

    int n = in_sizes[2];
    int e = in_sizes[1] / 2;

    float* out = (float*)d_out;
    float* out_nodes = out;
    float* out_graph = out + (size_t)n * 64;

    float *buf0, *buf1;
    cudaGetSymbolAddress((void**)&buf0, g_buf04);
    cudaGetSymbolAddress((void**)&buf1, g_buf14);

    k_init<<<(n + 255) / 256, 256>>>(out_graph, n);
    k_deg<<<(e + 255) / 256, 256>>>(ei, e);
    k_dis<<<(n + 255) / 256, 256>>>(batch, n);

    const float* xin = x;
    float* xouts[3] = {buf0, buf1, out_nodes};
    int scatter_blocks = (int)(((long long)e * 16 + 255) / 256);
    for (int l = 0; l < 3; l++) {
        k_gemm<<<(n + 63) / 64, 256>>>(xin, Ws[l], n);
        k_scatter<<<scatter_blocks, 256>>>(ei, e);
        k_epilogue<<<(n + 127) / 128, 256>>>(bs[l], batch, xouts[l], n);
        k_graphacc<<<16, 256>>>(out_graph);
        xin = xouts[l];
    }
}